// round 5
// baseline (speedup 1.0000x reference)
#include <cuda_runtime.h>
#include <cuda_bf16.h>
#include <cstdint>
#include <cstddef>

#define S_LEN 2048
#define R_LEN 384

// ms staging geometry (per warp): 4 groups (col&3) x 16 rows x 16 cols(>>2), padded
#define MS_ROW 18     // row stride in floats (even, padded from 16)
#define MS_G   296    // group stride in floats (16*18=288 + 8 for bank spread)
#define MS_WARP (4*MS_G)  // 1184 floats per warp

__device__ __forceinline__ unsigned tf32u(float x) {
    unsigned r; asm("cvt.rna.tf32.f32 %0, %1;" : "=r"(r) : "f"(x)); return r;
}
__device__ __forceinline__ float tf32f(float x) {
    unsigned r; asm("cvt.rna.tf32.f32 %0, %1;" : "=r"(r) : "f"(x)); return __uint_as_float(r);
}
__device__ __forceinline__ void mma_tf32(float c[4], unsigned a0, unsigned a1,
                                         unsigned a2, unsigned a3,
                                         unsigned b0, unsigned b1) {
    asm volatile(
        "mma.sync.aligned.m16n8k8.row.col.f32.tf32.tf32.f32 "
        "{%0,%1,%2,%3}, {%4,%5,%6,%7}, {%8,%9}, {%0,%1,%2,%3};\n"
        : "+f"(c[0]), "+f"(c[1]), "+f"(c[2]), "+f"(c[3])
        : "r"(a0), "r"(a1), "r"(a2), "r"(a3), "r"(b0), "r"(b1));
}

struct SmemAB {
    float mst[8][64];
    float pw[8][512];
    float wmax[8][8];
    float wZ[8][8];
    float msum[8];
    float pwt[512];
    float gmax[8];
    float Zt[8];
};

struct Smem {
    float WgF[4096];    // Wg in tf32, B-fragment order [kt][nt][lane][2]
    float WoF[4096];    // Wo in tf32, B-fragment order
    float Wv[512];      // [d][c]
    float qk[512];      // [h][d]
    union {
        SmemAB ab;
        float ms[8][MS_WARP];   // per-warp fragment staging (pass C)
    } u;
    float qpool[64];
    float oflat[64];
    float bgs[64];
    float bos[64];
    float qtmp[64];
    float msumtot;
};

__global__ void __launch_bounds__(256, 2)
msa_col_global_attn(const float* __restrict__ Mraw, const float* __restrict__ Mmask,
                    const float* __restrict__ ln_g, const float* __restrict__ ln_b,
                    const float* __restrict__ Wq,   const float* __restrict__ Wk,
                    const float* __restrict__ Wv,   const float* __restrict__ Wg,
                    const float* __restrict__ bg,   const float* __restrict__ Wo,
                    const float* __restrict__ bo,   float* __restrict__ Out)
{
    extern __shared__ char smraw[];
    Smem* sm = (Smem*)smraw;
    const int r    = blockIdx.x;
    const int tid  = threadIdx.x;
    const int lane = tid & 31;
    const int w    = tid >> 5;

    // ---- weight preamble: build tf32 B-fragments for Wg/Wo; plain loads for the rest ----
    {
        #pragma unroll
        for (int idx = tid; idx < 4096; idx += 256) {
            int j    = idx & 1;
            int L    = (idx >> 1) & 31;
            int ktnt = idx >> 6;            // kt*8+nt
            int kt = ktnt >> 3, nt = ktnt & 7;
            int kk = 8*kt + (L & 3) + 4*j;  // k index (d for Wg, hc for Wo)
            int nn = 8*nt + (L >> 2);       // n index (hc for Wg, d for Wo)
            sm->WgF[idx] = tf32f(__ldg(Wg + kk*64 + nn));
            sm->WoF[idx] = tf32f(__ldg(Wo + kk*64 + nn));
        }
        if (tid < 128) ((float4*)sm->Wv)[tid] = ((const float4*)Wv)[tid];
        if (tid < 64)  { sm->bgs[tid] = bg[tid]; sm->bos[tid] = bo[tid]; }
    }
    const float g0 = ln_g[2*lane], g1 = ln_g[2*lane+1];
    const float b0 = ln_b[2*lane], b1 = ln_b[2*lane+1];

    // ================= Pass A: LN + masked mean-pool =================
    {
        float qa0 = 0.f, qa1 = 0.f, msum = 0.f;
        float2 x  = *(const float2*)(Mraw + ((size_t)(w * R_LEN + r)) * 64 + 2*lane);
        float  mk = __ldg(Mmask + (size_t)w * R_LEN + r);
        for (int s = w; s < S_LEN; s += 8) {
            float2 cur = x; float cmk = mk;
            int sn = s + 8;
            if (sn < S_LEN) {
                x  = *(const float2*)(Mraw + ((size_t)(sn * R_LEN + r)) * 64 + 2*lane);
                mk = __ldg(Mmask + (size_t)sn * R_LEN + r);
            }
            float t = cur.x + cur.y, sq = fmaf(cur.x, cur.x, cur.y * cur.y);
            #pragma unroll
            for (int o = 16; o; o >>= 1) {
                t  += __shfl_xor_sync(0xffffffffu, t, o);
                sq += __shfl_xor_sync(0xffffffffu, sq, o);
            }
            float mu   = t * (1.f/64.f);
            float rstd = rsqrtf(fmaf(sq, 1.f/64.f, -mu*mu) + 1e-5f);
            float m0 = fmaf((cur.x - mu) * rstd, g0, b0);
            float m1 = fmaf((cur.y - mu) * rstd, g1, b1);
            qa0 = fmaf(cmk, m0, qa0);
            qa1 = fmaf(cmk, m1, qa1);
            msum += cmk;
        }
        *(float2*)&sm->u.ab.pw[w][2*lane] = make_float2(qa0, qa1);
        if (lane == 0) sm->u.ab.msum[w] = msum;
    }
    __syncthreads();
    if (tid < 64) {
        float a = 0.f;
        #pragma unroll
        for (int ww = 0; ww < 8; ww++) a += sm->u.ab.pw[ww][tid];
        sm->qpool[tid] = a;
    }
    if (tid == 64) {
        float a = 0.f;
        #pragma unroll
        for (int ww = 0; ww < 8; ww++) a += sm->u.ab.msum[ww];
        sm->msumtot = a;
    }
    __syncthreads();

    // q = (pool/msum) @ Wq * C^-0.5  (warp 0)
    if (w == 0) {
        const float inv = 1.f / (sm->msumtot + 1e-10f);
        float q0 = 0.f, q1 = 0.f;
        #pragma unroll 8
        for (int d = 0; d < 64; d++) {
            float qa = sm->qpool[d] * inv;
            float2 wq = __ldg((const float2*)(Wq + d*64 + 2*lane));
            q0 = fmaf(qa, wq.x, q0);
            q1 = fmaf(qa, wq.y, q1);
        }
        const float sc = 0.35355339059327373f;  // 8^-0.5
        sm->qtmp[2*lane]   = q0 * sc;
        sm->qtmp[2*lane+1] = q1 * sc;
    }
    __syncthreads();
    // qk[h][d] = sum_c q[h*8+c] * Wk[d][c]
    {
        const int h = w;
        float a0 = 0.f, a1 = 0.f;
        #pragma unroll
        for (int c = 0; c < 8; c++) {
            float qq = sm->qtmp[h*8 + c];
            a0 = fmaf(qq, __ldg(Wk + lane*8 + c),      a0);
            a1 = fmaf(qq, __ldg(Wk + (lane+32)*8 + c), a1);
        }
        sm->qk[h*64 + lane]      = a0;
        sm->qk[h*64 + lane + 32] = a1;
    }
    __syncthreads();

    // ================= Pass B: online softmax; pw[h][d] = sum_s w[h,s] m[s,d] =================
    {
        const int myh = lane >> 2, seg = lane & 3;
        const float4 qv0 = *(const float4*)&sm->qk[myh*64 + seg*16 +  0];
        const float4 qv1 = *(const float4*)&sm->qk[myh*64 + seg*16 +  4];
        const float4 qv2 = *(const float4*)&sm->qk[myh*64 + seg*16 +  8];
        const float4 qv3 = *(const float4*)&sm->qk[myh*64 + seg*16 + 12];
        float rmax = -3.4e38f, rZ = 0.f;
        float pwr[16];
        #pragma unroll
        for (int i = 0; i < 16; i++) pwr[i] = 0.f;

        float2 x  = *(const float2*)(Mraw + ((size_t)(w * R_LEN + r)) * 64 + 2*lane);
        float  mk = __ldg(Mmask + (size_t)w * R_LEN + r);
        for (int s = w; s < S_LEN; s += 8) {
            float2 cur = x; float cmk = mk;
            int sn = s + 8;
            if (sn < S_LEN) {
                x  = *(const float2*)(Mraw + ((size_t)(sn * R_LEN + r)) * 64 + 2*lane);
                mk = __ldg(Mmask + (size_t)sn * R_LEN + r);
            }
            float t = cur.x + cur.y, sq = fmaf(cur.x, cur.x, cur.y * cur.y);
            #pragma unroll
            for (int o = 16; o; o >>= 1) {
                t  += __shfl_xor_sync(0xffffffffu, t, o);
                sq += __shfl_xor_sync(0xffffffffu, sq, o);
            }
            float mu   = t * (1.f/64.f);
            float rstd = rsqrtf(fmaf(sq, 1.f/64.f, -mu*mu) + 1e-5f);
            float m0 = fmaf((cur.x - mu) * rstd, g0, b0);
            float m1 = fmaf((cur.y - mu) * rstd, g1, b1);
            *(float2*)&sm->u.ab.mst[w][2*lane] = make_float2(m0, m1);
            __syncwarp();
            const float4 A0 = *(const float4*)&sm->u.ab.mst[w][seg*16 +  0];
            const float4 A1 = *(const float4*)&sm->u.ab.mst[w][seg*16 +  4];
            const float4 A2 = *(const float4*)&sm->u.ab.mst[w][seg*16 +  8];
            const float4 A3 = *(const float4*)&sm->u.ab.mst[w][seg*16 + 12];
            float acc = A0.x * qv0.x;
            acc = fmaf(A0.y, qv0.y, acc); acc = fmaf(A0.z, qv0.z, acc); acc = fmaf(A0.w, qv0.w, acc);
            acc = fmaf(A1.x, qv1.x, acc); acc = fmaf(A1.y, qv1.y, acc);
            acc = fmaf(A1.z, qv1.z, acc); acc = fmaf(A1.w, qv1.w, acc);
            acc = fmaf(A2.x, qv2.x, acc); acc = fmaf(A2.y, qv2.y, acc);
            acc = fmaf(A2.z, qv2.z, acc); acc = fmaf(A2.w, qv2.w, acc);
            acc = fmaf(A3.x, qv3.x, acc); acc = fmaf(A3.y, qv3.y, acc);
            acc = fmaf(A3.z, qv3.z, acc); acc = fmaf(A3.w, qv3.w, acc);
            acc += __shfl_xor_sync(0xffffffffu, acc, 1);
            acc += __shfl_xor_sync(0xffffffffu, acc, 2);
            float logit = acc + 1e9f * (cmk - 1.f);
            if (logit > rmax) {
                float alpha = __expf(rmax - logit);
                rZ *= alpha;
                #pragma unroll
                for (int i = 0; i < 16; i++) pwr[i] *= alpha;
                rmax = logit;
            }
            float e = __expf(logit - rmax);
            rZ += e;
            pwr[ 0] = fmaf(e, A0.x, pwr[ 0]); pwr[ 1] = fmaf(e, A0.y, pwr[ 1]);
            pwr[ 2] = fmaf(e, A0.z, pwr[ 2]); pwr[ 3] = fmaf(e, A0.w, pwr[ 3]);
            pwr[ 4] = fmaf(e, A1.x, pwr[ 4]); pwr[ 5] = fmaf(e, A1.y, pwr[ 5]);
            pwr[ 6] = fmaf(e, A1.z, pwr[ 6]); pwr[ 7] = fmaf(e, A1.w, pwr[ 7]);
            pwr[ 8] = fmaf(e, A2.x, pwr[ 8]); pwr[ 9] = fmaf(e, A2.y, pwr[ 9]);
            pwr[10] = fmaf(e, A2.z, pwr[10]); pwr[11] = fmaf(e, A2.w, pwr[11]);
            pwr[12] = fmaf(e, A3.x, pwr[12]); pwr[13] = fmaf(e, A3.y, pwr[13]);
            pwr[14] = fmaf(e, A3.z, pwr[14]); pwr[15] = fmaf(e, A3.w, pwr[15]);
            __syncwarp();
        }
        *(float4*)&sm->u.ab.pw[w][myh*64 + seg*16 +  0] = make_float4(pwr[ 0], pwr[ 1], pwr[ 2], pwr[ 3]);
        *(float4*)&sm->u.ab.pw[w][myh*64 + seg*16 +  4] = make_float4(pwr[ 4], pwr[ 5], pwr[ 6], pwr[ 7]);
        *(float4*)&sm->u.ab.pw[w][myh*64 + seg*16 +  8] = make_float4(pwr[ 8], pwr[ 9], pwr[10], pwr[11]);
        *(float4*)&sm->u.ab.pw[w][myh*64 + seg*16 + 12] = make_float4(pwr[12], pwr[13], pwr[14], pwr[15]);
        if (seg == 0) { sm->u.ab.wmax[w][myh] = rmax; sm->u.ab.wZ[w][myh] = rZ; }
    }
    __syncthreads();

    // combine warps
    if (tid < 8) {
        int h = tid;
        float gm = -3.4e38f;
        #pragma unroll
        for (int ww = 0; ww < 8; ww++) gm = fmaxf(gm, sm->u.ab.wmax[ww][h]);
        float Z = 0.f;
        #pragma unroll
        for (int ww = 0; ww < 8; ww++) Z += sm->u.ab.wZ[ww][h] * __expf(sm->u.ab.wmax[ww][h] - gm);
        sm->u.ab.gmax[h] = gm;
        sm->u.ab.Zt[h]   = Z;
    }
    __syncthreads();
    #pragma unroll
    for (int ii = 0; ii < 2; ii++) {
        int idx = tid + ii * 256;
        int h = idx >> 6;
        float gm = sm->u.ab.gmax[h];
        float a = 0.f;
        #pragma unroll
        for (int ww = 0; ww < 8; ww++)
            a = fmaf(sm->u.ab.pw[ww][idx], __expf(sm->u.ab.wmax[ww][h] - gm), a);
        sm->u.ab.pwt[idx] = a;
    }
    __syncthreads();
    // o[hc] = (pwt[h] @ Wv)[c] / Z[h]
    if (tid < 64) {
        int h = tid >> 3, c = tid & 7;
        float a = 0.f;
        #pragma unroll 8
        for (int d = 0; d < 64; d++) a = fmaf(sm->u.ab.pwt[h*64 + d], sm->Wv[d*8 + c], a);
        sm->oflat[tid] = a / sm->u.ab.Zt[h];
    }
    __syncthreads();

    // ================= Pass C: tensor-core gate + output projection + residual =================
    {
        float* ms = sm->u.ms[w];
        const int x3 = lane & 3, r0 = lane >> 2;
        const int sg2 = 2*(lane & 1), ih = lane >> 1;        // LN store indices
        const int aoff = x3*MS_G + r0*MS_ROW;                // A-frag base
        const int gsel = (2*x3) & 3;                         // go restage group

        for (int t = w; t < 128; t += 8) {
            const int sbase = t * 16;
            // ---- LN 16 rows -> fragment staging ----
            #pragma unroll 4
            for (int j = 0; j < 16; j++) {
                float2 cur = *(const float2*)(Mraw + ((size_t)((sbase + j) * R_LEN + r)) * 64 + 2*lane);
                float tt = cur.x + cur.y, sq = fmaf(cur.x, cur.x, cur.y * cur.y);
                #pragma unroll
                for (int o = 16; o; o >>= 1) {
                    tt += __shfl_xor_sync(0xffffffffu, tt, o);
                    sq += __shfl_xor_sync(0xffffffffu, sq, o);
                }
                float mu   = tt * (1.f/64.f);
                float rstd = rsqrtf(fmaf(sq, 1.f/64.f, -mu*mu) + 1e-5f);
                ms[sg2*MS_G     + j*MS_ROW + ih] = fmaf((cur.x - mu) * rstd, g0, b0);
                ms[(sg2+1)*MS_G + j*MS_ROW + ih] = fmaf((cur.y - mu) * rstd, g1, b1);
            }
            __syncwarp();

            float acc[8][4];
            #pragma unroll
            for (int nt = 0; nt < 8; nt++)
                #pragma unroll
                for (int i = 0; i < 4; i++) acc[nt][i] = 0.f;

            // ---- GEMM1: G = m @ Wg ----
            #pragma unroll
            for (int kt = 0; kt < 8; kt++) {
                float2 lo = *(const float2*)&ms[aoff + 2*kt];
                float2 hi = *(const float2*)&ms[aoff + 8*MS_ROW + 2*kt];
                unsigned a0 = tf32u(lo.x), a2 = tf32u(lo.y);
                unsigned a1 = tf32u(hi.x), a3 = tf32u(hi.y);
                #pragma unroll
                for (int nt = 0; nt < 8; nt++) {
                    float2 bf = *(const float2*)&sm->WgF[(kt*8+nt)*64 + lane*2];
                    mma_tf32(acc[nt], a0, a1, a2, a3,
                             __float_as_uint(bf.x), __float_as_uint(bf.y));
                }
            }
            __syncwarp();

            // ---- sigmoid gate * o, restage as A-frags for GEMM2 ----
            #pragma unroll
            for (int nt = 0; nt < 8; nt++) {
                float2 bgp = *(const float2*)&sm->bgs[8*nt + 2*x3];
                float2 oop = *(const float2*)&sm->oflat[8*nt + 2*x3];
                float gc0 = oop.x / (1.f + __expf(-(acc[nt][0] + bgp.x)));
                float gc1 = oop.y / (1.f + __expf(-(acc[nt][1] + bgp.y)));
                float gc2 = oop.x / (1.f + __expf(-(acc[nt][2] + bgp.x)));
                float gc3 = oop.y / (1.f + __expf(-(acc[nt][3] + bgp.y)));
                float* p = ms + gsel*MS_G + 2*nt + (x3 >> 1);
                p[r0*MS_ROW]                 = gc0;
                p[MS_G + r0*MS_ROW]          = gc1;
                p[(r0+8)*MS_ROW]             = gc2;
                p[MS_G + (r0+8)*MS_ROW]      = gc3;
            }
            __syncwarp();

            #pragma unroll
            for (int nt = 0; nt < 8; nt++)
                #pragma unroll
                for (int i = 0; i < 4; i++) acc[nt][i] = 0.f;

            // ---- GEMM2: out = go @ Wo ----
            #pragma unroll
            for (int kt = 0; kt < 8; kt++) {
                float2 lo = *(const float2*)&ms[aoff + 2*kt];
                float2 hi = *(const float2*)&ms[aoff + 8*MS_ROW + 2*kt];
                unsigned a0 = tf32u(lo.x), a2 = tf32u(lo.y);
                unsigned a1 = tf32u(hi.x), a3 = tf32u(hi.y);
                #pragma unroll
                for (int nt = 0; nt < 8; nt++) {
                    float2 bf = *(const float2*)&sm->WoF[(kt*8+nt)*64 + lane*2];
                    mma_tf32(acc[nt], a0, a1, a2, a3,
                             __float_as_uint(bf.x), __float_as_uint(bf.y));
                }
            }

            // ---- epilogue: + bo + residual, store ----
            #pragma unroll
            for (int nt = 0; nt < 8; nt++) {
                int d0 = 8*nt + 2*x3;
                float2 bop = *(const float2*)&sm->bos[d0];
                size_t base0 = ((size_t)((sbase + r0)     * R_LEN + r)) * 64 + d0;
                size_t base1 = ((size_t)((sbase + r0 + 8) * R_LEN + r)) * 64 + d0;
                float2 x0 = *(const float2*)(Mraw + base0);
                float2 x1 = *(const float2*)(Mraw + base1);
                *(float2*)(Out + base0) = make_float2(acc[nt][0] + bop.x + x0.x,
                                                      acc[nt][1] + bop.y + x0.y);
                *(float2*)(Out + base1) = make_float2(acc[nt][2] + bop.x + x1.x,
                                                      acc[nt][3] + bop.y + x1.y);
            }
            __syncwarp();
        }
    }
}

extern "C" void kernel_launch(void* const* d_in, const int* in_sizes, int n_in,
                              void* d_out, int out_size) {
    const float* Mraw  = (const float*)d_in[0];
    const float* Mmask = (const float*)d_in[1];
    const float* ln_g  = (const float*)d_in[2];
    const float* ln_b  = (const float*)d_in[3];
    const float* Wq    = (const float*)d_in[4];
    const float* Wk    = (const float*)d_in[5];
    const float* Wv    = (const float*)d_in[6];
    const float* Wg    = (const float*)d_in[7];
    const float* bg    = (const float*)d_in[8];
    const float* Wo    = (const float*)d_in[9];
    const float* bo    = (const float*)d_in[10];
    float* Out = (float*)d_out;

    cudaFuncSetAttribute(msa_col_global_attn,
                         cudaFuncAttributeMaxDynamicSharedMemorySize,
                         (int)sizeof(Smem));
    msa_col_global_attn<<<R_LEN, 256, sizeof(Smem)>>>(
        Mraw, Mmask, ln_g, ln_b, Wq, Wk, Wv, Wg, bg, Wo, bo, Out);
}